// round 14
// baseline (speedup 1.0000x reference)
#include <cuda_runtime.h>
#include <cstdint>

// Problem constants (shapes fixed by the dataset)
#define SQ 50          // qubits
#define SP 3           // pauli basis
#define SS 64          // heads
#define WORDS 256      // words per block
#define THREADS 512    // 16 warps; warp quads split 64 heads, 2 words/thread
#define TROW 156       // padded row stride (28i mod 32: 8-lane LDS.128 phases disjoint)

// Packed heads: ha[q][j(32)][4] = {h0s0,h0s1,h1s0,h1s1}
//               hcp[q][jp(16)][4] = {h2(2jp)s0,h2(2jp)s1, h2(2jp+1)s0,h2(2jp+1)s1}
#define HA_TOTAL (SQ * 128)   // 6400
#define HCP_TOTAL (SQ * 64)   // 3200

// smem float offsets
#define OFF_HCP  HA_TOTAL               // 6400
#define OFF_HR   (OFF_HCP + HCP_TOTAL)  // 9600
#define OFF_PART (OFF_HR + SS)          // 9664 (3*256 = 768)
#define OFF_RED  (OFF_PART + 3*WORDS)   // 10432 (16 floats = 8 doubles)
#define OFF_T    (OFF_RED + 16)         // 10448 (41792 B, 16B aligned)
#define SMEM_FLOATS (OFF_T + WORDS * TROW)   // 50384 floats = 201536 B

__device__ double       g_accum;   // static zero-init; ticket block resets after use
__device__ unsigned int g_count;

__device__ __forceinline__ float softplus20(float x) {
    float y = x * 20.0f;
    return fmaxf(y, 0.0f) + log1pf(expf(-fabsf(y)));
}

// ---------------------------------------------------------------------------
// Per-q step: 2 words x 8 head-pairs. dot = t2c*(h2 + h0*(t0/t2c) + h1*(t1/t2c))
// ---------------------------------------------------------------------------
__device__ __forceinline__ void proc_q2(
    bool do_p2, bool first_half,
    float t0a, float t1a, float t2a,     // word A
    float t0b, float t1b, float t2b,     // word B
    const ulonglong2* __restrict__ ha,   // this q, quarter offset: 8 entries
    const ulonglong2* __restrict__ hcp,  // this q, quarter offset: 4 entries
    uint64_t* __restrict__ accA, uint64_t* __restrict__ accB,
    float& pAa, float& pAb, float& pBa, float& pBb)
{
    float t2ca = fmaxf(t2a, 1e-12f);
    float t2cb = fmaxf(t2b, 1e-12f);
    float ra, rb;
    asm("rcp.approx.f32 %0, %1;" : "=f"(ra) : "f"(t2ca));
    asm("rcp.approx.f32 %0, %1;" : "=f"(rb) : "f"(t2cb));
    float r0a = t0a * ra, r1a = t1a * ra;
    float r0b = t0b * rb, r1b = t1b * rb;
    if (do_p2) {
        if (first_half) { pAa *= t2ca; pBa *= t2cb; }
        else            { pAb *= t2ca; pBb *= t2cb; }
    }

    uint64_t R0A, R1A, R0B, R1B;
    asm("mov.b64 %0, {%1, %1};" : "=l"(R0A) : "f"(r0a));
    asm("mov.b64 %0, {%1, %1};" : "=l"(R1A) : "f"(r1a));
    asm("mov.b64 %0, {%1, %1};" : "=l"(R0B) : "f"(r0b));
    asm("mov.b64 %0, {%1, %1};" : "=l"(R1B) : "f"(r1b));

    #pragma unroll
    for (int jp = 0; jp < 4; jp++) {
        ulonglong2 HcP = hcp[jp];          // {h2(2jp) pair, h2(2jp+1) pair}
        ulonglong2 Ha0 = ha[2 * jp];
        ulonglong2 Ha1 = ha[2 * jp + 1];
        uint64_t dA, dB;
        // j = 2jp
        asm("fma.rn.f32x2 %0, %1, %2, %3;" : "=l"(dA) : "l"(Ha0.x), "l"(R0A), "l"(HcP.x));
        asm("fma.rn.f32x2 %0, %1, %2, %3;" : "=l"(dB) : "l"(Ha0.x), "l"(R0B), "l"(HcP.x));
        asm("fma.rn.f32x2 %0, %1, %2, %3;" : "=l"(dA) : "l"(Ha0.y), "l"(R1A), "l"(dA));
        asm("fma.rn.f32x2 %0, %1, %2, %3;" : "=l"(dB) : "l"(Ha0.y), "l"(R1B), "l"(dB));
        asm("mul.rn.f32x2 %0, %1, %2;" : "=l"(accA[2*jp]) : "l"(accA[2*jp]), "l"(dA));
        asm("mul.rn.f32x2 %0, %1, %2;" : "=l"(accB[2*jp]) : "l"(accB[2*jp]), "l"(dB));
        // j = 2jp+1
        asm("fma.rn.f32x2 %0, %1, %2, %3;" : "=l"(dA) : "l"(Ha1.x), "l"(R0A), "l"(HcP.y));
        asm("fma.rn.f32x2 %0, %1, %2, %3;" : "=l"(dB) : "l"(Ha1.x), "l"(R0B), "l"(HcP.y));
        asm("fma.rn.f32x2 %0, %1, %2, %3;" : "=l"(dA) : "l"(Ha1.y), "l"(R1A), "l"(dA));
        asm("fma.rn.f32x2 %0, %1, %2, %3;" : "=l"(dB) : "l"(Ha1.y), "l"(R1B), "l"(dB));
        asm("mul.rn.f32x2 %0, %1, %2;" : "=l"(accA[2*jp+1]) : "l"(accA[2*jp+1]), "l"(dA));
        asm("mul.rn.f32x2 %0, %1, %2;" : "=l"(accB[2*jp+1]) : "l"(accB[2*jp+1]), "l"(dB));
    }
}

// ---------------------------------------------------------------------------
// Single fused kernel. Warp quad g=wid>>2 covers words [g*64, g*64+64);
// quarter = wid&3 handles head pairs quarter*8..+7. Thread words: lane, lane+32.
// ---------------------------------------------------------------------------
__global__ void __launch_bounds__(THREADS, 1)
main_kernel(const float* __restrict__ pauli,
            const float* __restrict__ coeff,
            const float* __restrict__ heads_param,
            const float* __restrict__ hr_param,
            float* __restrict__ out,
            int N, int nblocks) {
    extern __shared__ float smem[];
    float*  sh_ha   = smem;
    float*  sh_hcp  = smem + OFF_HCP;
    float*  sh_hr   = smem + OFF_HR;
    float*  sh_part = smem + OFF_PART;
    double* sh_red  = (double*)(smem + OFF_RED);
    float*  sh_t    = smem + OFF_T;

    const int tid  = threadIdx.x;
    const int wid  = tid >> 5;
    const int lane = tid & 31;

    // ---- 1. Issue t-tile staging via cp.async (8B chunks; all 8B-aligned) ----
    const int base  = blockIdx.x * WORDS;
    const int valid = min(WORDS, N - base);
    const float* gsrc = pauli + (size_t)base * (SQ * SP);
    for (int i = tid; i < valid * 75; i += THREADS) {
        int w = i / 75;
        int k = i - w * 75;
        unsigned dst = (unsigned)__cvta_generic_to_shared(sh_t + w * TROW + 2 * k);
        const float* src = gsrc + 2 * i - 2 * (w * 75) + (size_t)w * 150;  // = gsrc + w*150 + 2k
        asm volatile("cp.async.ca.shared.global [%0], [%1], 8;" :: "r"(dst), "l"(src));
    }

    // ---- 2. Build heads tables in smem (overlaps with cp.async in flight) ----
    for (int i = tid; i < SS * SQ; i += THREADS) {
        int s = i / SQ;
        int q = i - s * SQ;
        const float* hp = heads_param + (s * SQ + q) * SP;
        float h0 = softplus20(hp[0]);
        float h1 = softplus20(hp[1]);
        float h2 = softplus20(hp[2]);
        float inv = 1.0f / fmaxf(h0 + h1 + h2, 1e-12f);
        h0 *= inv; h1 *= inv; h2 *= inv;
        int j = s >> 1, o = s & 1;
        int jp = j >> 1, jo = j & 1;
        sh_ha[q * 128 + j * 4 + 0 + o]       = h0;
        sh_ha[q * 128 + j * 4 + 2 + o]       = h1;
        sh_hcp[q * 64 + jp * 4 + jo * 2 + o] = h2;
    }
    // raw hr softplus into sh_part (scratch; reused for partials later)
    if (tid < SS) sh_part[tid] = softplus20(hr_param[tid]);

    asm volatile("cp.async.wait_all;" ::: "memory");
    __syncthreads();

    // ---- 3. Finalize hr (same op order as before: sequential sum 0..63) ----
    if (tid < SS) {
        float s = 0.0f;
        #pragma unroll
        for (int i = 0; i < SS; i++) s += sh_part[i];
        s = fmaxf(s, 1e-12f);
        sh_hr[tid] = (sh_part[tid] / s + 0.001f / (float)SS) / 1.001f;
    }
    __syncthreads();

    // ---- 4. Main loop (R12 verbatim) ----
    const int quarter = wid & 3;
    const int group   = wid >> 2;
    const int wA = group * 64 + lane;
    const int wB = wA + 32;
    const float* trowA = sh_t + wA * TROW;
    const float* trowB = sh_t + wB * TROW;
    const bool do_p2 = (quarter == 0);   // warp-uniform

    uint64_t accA[8], accB[8];
    #pragma unroll
    for (int j = 0; j < 8; j++) { accA[j] = 0x3F8000003F800000ull; accB[j] = accA[j]; }
    float pAa = 1.0f, pAb = 1.0f, pBa = 1.0f, pBb = 1.0f;

    const ulonglong2* ha_q  = (const ulonglong2*)sh_ha  + quarter * 8;   // + q*32
    const ulonglong2* hcp_q = (const ulonglong2*)sh_hcp + quarter * 4;   // + q*16

    const float4* tvA = (const float4*)trowA;
    const float4* tvB = (const float4*)trowB;
    #pragma unroll 4
    for (int c = 0; c < 12; c++) {
        float4 A0 = tvA[3*c+0], A1 = tvA[3*c+1], A2 = tvA[3*c+2];
        float4 B0 = tvB[3*c+0], B1 = tvB[3*c+1], B2 = tvB[3*c+2];
        const int q = 4 * c;
        proc_q2(do_p2, q + 0 < 25, A0.x, A0.y, A0.z, B0.x, B0.y, B0.z,
                ha_q + (q+0)*32, hcp_q + (q+0)*16, accA, accB, pAa, pAb, pBa, pBb);
        proc_q2(do_p2, q + 1 < 25, A0.w, A1.x, A1.y, B0.w, B1.x, B1.y,
                ha_q + (q+1)*32, hcp_q + (q+1)*16, accA, accB, pAa, pAb, pBa, pBb);
        proc_q2(do_p2, q + 2 < 25, A1.z, A1.w, A2.x, B1.z, B1.w, B2.x,
                ha_q + (q+2)*32, hcp_q + (q+2)*16, accA, accB, pAa, pAb, pBa, pBb);
        proc_q2(do_p2, q + 3 < 25, A2.y, A2.z, A2.w, B2.y, B2.z, B2.w,
                ha_q + (q+3)*32, hcp_q + (q+3)*16, accA, accB, pAa, pAb, pBa, pBb);
    }
    {   // q = 48, 49 (floats 144..149, 8B-aligned)
        const float2* a2 = (const float2*)(trowA + 144);
        const float2* b2 = (const float2*)(trowB + 144);
        float2 ua = a2[0], va = a2[1], wa2 = a2[2];
        float2 ub = b2[0], vb = b2[1], wb2 = b2[2];
        proc_q2(do_p2, false, ua.x, ua.y, va.x, ub.x, ub.y, vb.x,
                ha_q + 48*32, hcp_q + 48*16, accA, accB, pAa, pAb, pBa, pBb);
        proc_q2(do_p2, false, va.y, wa2.x, wa2.y, vb.y, wb2.x, wb2.y,
                ha_q + 49*32, hcp_q + 49*16, accA, accB, pAa, pAb, pBa, pBb);
    }

    // hr-weighted sums over this quarter's 16 heads
    float partA = 0.0f, partB = 0.0f;
    const float* hrq = sh_hr + quarter * 16;
    #pragma unroll
    for (int j = 0; j < 8; j++) {
        float lo, hi;
        asm("mov.b64 {%0, %1}, %2;" : "=f"(lo), "=f"(hi) : "l"(accA[j]));
        partA = fmaf(hrq[2 * j], lo, partA);
        partA = fmaf(hrq[2 * j + 1], hi, partA);
        asm("mov.b64 {%0, %1}, %2;" : "=f"(lo), "=f"(hi) : "l"(accB[j]));
        partB = fmaf(hrq[2 * j], lo, partB);
        partB = fmaf(hrq[2 * j + 1], hi, partB);
    }

    __syncthreads();   // sh_part scratch (hr raw) is done being read; reuse
    if (quarter != 0) {
        sh_part[(quarter - 1) * WORDS + wA] = partA;
        sh_part[(quarter - 1) * WORDS + wB] = partB;
    }
    __syncthreads();

    double v = 0.0;
    if (quarter == 0) {
        int nA = base + wA;
        if (nA < N) {
            float covf = partA + sh_part[wA] + sh_part[WORDS + wA] + sh_part[2 * WORDS + wA];
            double cov = (double)covf * (double)pAa * (double)pAb;
            float c = coeff[nA];
            v = (double)(c * c) / cov;
        }
        int nB = base + wB;
        if (nB < N) {
            float covf = partB + sh_part[wB] + sh_part[WORDS + wB] + sh_part[2 * WORDS + wB];
            double cov = (double)covf * (double)pBa * (double)pBb;
            float c = coeff[nB];
            v += (double)(c * c) / cov;
        }
        #pragma unroll
        for (int off = 16; off; off >>= 1)
            v += __shfl_down_sync(0xFFFFFFFFu, v, off);
        if (lane == 0) sh_red[group] = v;
    }
    __syncthreads();
    if (tid == 0) {
        double s = 0.0;
        #pragma unroll
        for (int w = 0; w < 4; w++) s += sh_red[w];
        atomicAdd(&g_accum, s);
        __threadfence();
        unsigned int ticket = atomicAdd(&g_count, 1u);
        if (ticket == (unsigned int)(nblocks - 1)) {
            out[0] = (float)g_accum;
            // reset for next graph replay (no other block touches these anymore)
            g_accum = 0.0;
            g_count = 0u;
        }
    }
}

// ---------------------------------------------------------------------------
extern "C" void kernel_launch(void* const* d_in, const int* in_sizes, int n_in,
                              void* d_out, int out_size) {
    const float* pauli = (const float*)d_in[0];   // [N, 50, 3] f32
    const float* coeff = (const float*)d_in[1];   // [N] f32
    const float* heads = (const float*)d_in[2];   // [64, 50, 3] f32
    const float* hr    = (const float*)d_in[3];   // [64] f32
    const int N = in_sizes[1];

    const size_t smem = (size_t)SMEM_FLOATS * sizeof(float);   // 201536 B
    cudaFuncSetAttribute(main_kernel, cudaFuncAttributeMaxDynamicSharedMemorySize, (int)smem);

    const int grid = (N + WORDS - 1) / WORDS;
    main_kernel<<<grid, THREADS, smem>>>(pauli, coeff, heads, hr, (float*)d_out, N, grid);
}

// round 15
// speedup vs baseline: 1.0786x; 1.0786x over previous
#include <cuda_runtime.h>
#include <cstdint>

// Problem constants (shapes fixed by the dataset)
#define SQ 50          // qubits
#define SP 3           // pauli basis
#define SS 64          // heads
#define WORDS 256      // words per block
#define THREADS 512    // 16 warps; warp quads split 64 heads, 2 words/thread
#define TROW 156       // padded row stride (28i mod 32: 8-lane LDS.128 phases disjoint)

// Packed heads: ha[q][j(32)][4] = {h0s0,h0s1,h1s0,h1s1}
//               hcp[q][jp(16)][4] = {h2(2jp)s0,h2(2jp)s1, h2(2jp+1)s0,h2(2jp+1)s1}
#define HA_TOTAL (SQ * 128)   // 6400
#define HCP_TOTAL (SQ * 64)   // 3200

// smem float offsets
#define OFF_HCP  HA_TOTAL               // 6400
#define OFF_HR   (OFF_HCP + HCP_TOTAL)  // 9600
#define OFF_PART (OFF_HR + SS)          // 9664 (3*256 = 768)
#define OFF_RED  (OFF_PART + 3*WORDS)   // 10432 (16 floats = 8 doubles)
#define OFF_T    (OFF_RED + 16)         // 10448 (41792 B, 16B aligned)
#define SMEM_FLOATS (OFF_T + WORDS * TROW)   // 50384 floats = 201536 B

__device__ double       g_accum;
__device__ unsigned int g_count;
__device__ float        g_ha[HA_TOTAL];
__device__ float        g_hcp[HCP_TOTAL];
__device__ float        g_hr[SS];

__device__ __forceinline__ float softplus20(float x) {
    float y = x * 20.0f;
    return fmaxf(y, 0.0f) + log1pf(expf(-fabsf(y)));
}

// ---------------------------------------------------------------------------
__global__ void prep_kernel(const float* __restrict__ heads_param,
                            const float* __restrict__ hr_param) {
    const int tid = threadIdx.x;

    if (blockIdx.x == 0 && tid == 0) { g_accum = 0.0; g_count = 0u; }

    __shared__ float s_hr[SS];
    if (tid < SS) s_hr[tid] = softplus20(hr_param[tid]);
    __syncthreads();
    if (blockIdx.x == 0 && tid < SS) {
        float s = 0.0f;
        #pragma unroll
        for (int i = 0; i < SS; i++) s += s_hr[i];
        s = fmaxf(s, 1e-12f);
        g_hr[tid] = (s_hr[tid] / s + 0.001f / (float)SS) / 1.001f;
    }

    const int stride = blockDim.x * gridDim.x;
    for (int i = blockIdx.x * blockDim.x + tid; i < SS * SQ; i += stride) {
        int s = i / SQ;
        int q = i - s * SQ;
        const float* hp = heads_param + (s * SQ + q) * SP;
        float h0 = softplus20(hp[0]);
        float h1 = softplus20(hp[1]);
        float h2 = softplus20(hp[2]);
        float inv = 1.0f / fmaxf(h0 + h1 + h2, 1e-12f);
        h0 *= inv; h1 *= inv; h2 *= inv;
        int j = s >> 1, o = s & 1;
        int jp = j >> 1, jo = j & 1;
        g_ha[q * 128 + j * 4 + 0 + o]       = h0;
        g_ha[q * 128 + j * 4 + 2 + o]       = h1;
        g_hcp[q * 64 + jp * 4 + jo * 2 + o] = h2;
    }
}

// ---------------------------------------------------------------------------
// Scalar r-chain for one q, both words -> 4 packed (x,x) f32x2 registers.
// ---------------------------------------------------------------------------
__device__ __forceinline__ void comp_r(
    bool do_p2, bool first_half,
    float t0a, float t1a, float t2a,
    float t0b, float t1b, float t2b,
    uint64_t& R0A, uint64_t& R1A, uint64_t& R0B, uint64_t& R1B,
    float& pAa, float& pAb, float& pBa, float& pBb)
{
    float t2ca = fmaxf(t2a, 1e-12f);
    float t2cb = fmaxf(t2b, 1e-12f);
    float ra, rb;
    asm("rcp.approx.f32 %0, %1;" : "=f"(ra) : "f"(t2ca));
    asm("rcp.approx.f32 %0, %1;" : "=f"(rb) : "f"(t2cb));
    float r0a = t0a * ra, r1a = t1a * ra;
    float r0b = t0b * rb, r1b = t1b * rb;
    if (do_p2) {
        if (first_half) { pAa *= t2ca; pBa *= t2cb; }
        else            { pAb *= t2ca; pBb *= t2cb; }
    }
    asm("mov.b64 %0, {%1, %1};" : "=l"(R0A) : "f"(r0a));
    asm("mov.b64 %0, {%1, %1};" : "=l"(R1A) : "f"(r1a));
    asm("mov.b64 %0, {%1, %1};" : "=l"(R0B) : "f"(r0b));
    asm("mov.b64 %0, {%1, %1};" : "=l"(R1B) : "f"(r1b));
}

// ---------------------------------------------------------------------------
// FMA block for one q, both words x 8 head-pairs, from prepacked r registers.
// ---------------------------------------------------------------------------
__device__ __forceinline__ void fma_q(
    const ulonglong2* __restrict__ ha,   // this q, quarter offset: 8 entries
    const ulonglong2* __restrict__ hcp,  // this q, quarter offset: 4 entries
    uint64_t R0A, uint64_t R1A, uint64_t R0B, uint64_t R1B,
    uint64_t* __restrict__ accA, uint64_t* __restrict__ accB)
{
    #pragma unroll
    for (int jp = 0; jp < 4; jp++) {
        ulonglong2 HcP = hcp[jp];
        ulonglong2 Ha0 = ha[2 * jp];
        ulonglong2 Ha1 = ha[2 * jp + 1];
        uint64_t dA, dB;
        asm("fma.rn.f32x2 %0, %1, %2, %3;" : "=l"(dA) : "l"(Ha0.x), "l"(R0A), "l"(HcP.x));
        asm("fma.rn.f32x2 %0, %1, %2, %3;" : "=l"(dB) : "l"(Ha0.x), "l"(R0B), "l"(HcP.x));
        asm("fma.rn.f32x2 %0, %1, %2, %3;" : "=l"(dA) : "l"(Ha0.y), "l"(R1A), "l"(dA));
        asm("fma.rn.f32x2 %0, %1, %2, %3;" : "=l"(dB) : "l"(Ha0.y), "l"(R1B), "l"(dB));
        asm("mul.rn.f32x2 %0, %1, %2;" : "=l"(accA[2*jp]) : "l"(accA[2*jp]), "l"(dA));
        asm("mul.rn.f32x2 %0, %1, %2;" : "=l"(accB[2*jp]) : "l"(accB[2*jp]), "l"(dB));
        asm("fma.rn.f32x2 %0, %1, %2, %3;" : "=l"(dA) : "l"(Ha1.x), "l"(R0A), "l"(HcP.y));
        asm("fma.rn.f32x2 %0, %1, %2, %3;" : "=l"(dB) : "l"(Ha1.x), "l"(R0B), "l"(HcP.y));
        asm("fma.rn.f32x2 %0, %1, %2, %3;" : "=l"(dA) : "l"(Ha1.y), "l"(R1A), "l"(dA));
        asm("fma.rn.f32x2 %0, %1, %2, %3;" : "=l"(dB) : "l"(Ha1.y), "l"(R1B), "l"(dB));
        asm("mul.rn.f32x2 %0, %1, %2;" : "=l"(accA[2*jp+1]) : "l"(accA[2*jp+1]), "l"(dA));
        asm("mul.rn.f32x2 %0, %1, %2;" : "=l"(accB[2*jp+1]) : "l"(accB[2*jp+1]), "l"(dB));
    }
}

// ---------------------------------------------------------------------------
// Main: warp quad g=wid>>2 covers words [g*64, g*64+64); quarter = wid&3
// handles head pairs quarter*8..+7. Thread words: lane, lane+32.
// Software pipeline: chunk c's fma interleaved with chunk c+1's t-load + r-chain.
// ---------------------------------------------------------------------------
__global__ void __launch_bounds__(THREADS, 1)
main_kernel(const float* __restrict__ pauli,
            const float* __restrict__ coeff,
            float* __restrict__ out,
            int N, int nblocks) {
    extern __shared__ float smem[];
    float*  sh_ha   = smem;
    float*  sh_hcp  = smem + OFF_HCP;
    float*  sh_hr   = smem + OFF_HR;
    float*  sh_part = smem + OFF_PART;
    double* sh_red  = (double*)(smem + OFF_RED);
    float*  sh_t    = smem + OFF_T;

    const int tid  = threadIdx.x;
    const int wid  = tid >> 5;
    const int lane = tid & 31;

    // Stage heads tables
    {
        const float4* src = (const float4*)g_ha;
        float4*       dst = (float4*)sh_ha;
        #pragma unroll
        for (int i = tid; i < HA_TOTAL / 4; i += THREADS) dst[i] = src[i];
        const float4* src2 = (const float4*)g_hcp;
        float4*       dst2 = (float4*)sh_hcp;
        #pragma unroll
        for (int i = tid; i < HCP_TOTAL / 4; i += THREADS) dst2[i] = src2[i];
    }
    if (tid < SS) sh_hr[tid] = g_hr[tid];

    // Stage pauli tile: float2 coalesced reads, padded-row float2 scatter
    const int base  = blockIdx.x * WORDS;
    const int valid = min(WORDS, N - base);
    const float2* gsrc2 = (const float2*)(pauli + (size_t)base * (SQ * SP));
    for (int i = tid; i < valid * 75; i += THREADS) {
        int w = i / 75;
        int k = i - w * 75;
        *(float2*)(sh_t + w * TROW + 2 * k) = gsrc2[i];
    }
    __syncthreads();

    const int quarter = wid & 3;
    const int group   = wid >> 2;
    const int wA = group * 64 + lane;
    const int wB = wA + 32;
    const bool do_p2 = (quarter == 0);   // warp-uniform

    uint64_t accA[8], accB[8];
    #pragma unroll
    for (int j = 0; j < 8; j++) { accA[j] = 0x3F8000003F800000ull; accB[j] = accA[j]; }
    float pAa = 1.0f, pAb = 1.0f, pBa = 1.0f, pBb = 1.0f;

    const ulonglong2* ha_q  = (const ulonglong2*)sh_ha  + quarter * 8;   // + q*32
    const ulonglong2* hcp_q = (const ulonglong2*)sh_hcp + quarter * 4;   // + q*16

    const float4* tvA = (const float4*)(sh_t + wA * TROW);
    const float4* tvB = (const float4*)(sh_t + wB * TROW);

    // r registers for 4 in-flight q (each q: 4 packs)
    uint64_t Rr[16];

    // ---- Prologue: chunk 0 (q 0..3) ----
    {
        float4 A0 = tvA[0], A1 = tvA[1], A2 = tvA[2];
        float4 B0 = tvB[0], B1 = tvB[1], B2 = tvB[2];
        comp_r(do_p2, true, A0.x, A0.y, A0.z, B0.x, B0.y, B0.z,
               Rr[0], Rr[1], Rr[2], Rr[3], pAa, pAb, pBa, pBb);
        comp_r(do_p2, true, A0.w, A1.x, A1.y, B0.w, B1.x, B1.y,
               Rr[4], Rr[5], Rr[6], Rr[7], pAa, pAb, pBa, pBb);
        comp_r(do_p2, true, A1.z, A1.w, A2.x, B1.z, B1.w, B2.x,
               Rr[8], Rr[9], Rr[10], Rr[11], pAa, pAb, pBa, pBb);
        comp_r(do_p2, true, A2.y, A2.z, A2.w, B2.y, B2.z, B2.w,
               Rr[12], Rr[13], Rr[14], Rr[15], pAa, pAb, pBa, pBb);
    }

    // ---- Steady state: c = 0..10 process chunk c, prefetch chunk c+1 ----
    #pragma unroll 1
    for (int c = 0; c < 11; c++) {
        const int q = 4 * c;
        // prefetch chunk c+1 t-values (float4, conflict-free)
        float4 A0 = tvA[3*c+3], A1 = tvA[3*c+4], A2 = tvA[3*c+5];
        float4 B0 = tvB[3*c+3], B1 = tvB[3*c+4], B2 = tvB[3*c+5];

        fma_q(ha_q + (q+0)*32, hcp_q + (q+0)*16, Rr[0], Rr[1], Rr[2], Rr[3], accA, accB);
        fma_q(ha_q + (q+1)*32, hcp_q + (q+1)*16, Rr[4], Rr[5], Rr[6], Rr[7], accA, accB);

        comp_r(do_p2, q + 4 < 25, A0.x, A0.y, A0.z, B0.x, B0.y, B0.z,
               Rr[0], Rr[1], Rr[2], Rr[3], pAa, pAb, pBa, pBb);
        comp_r(do_p2, q + 5 < 25, A0.w, A1.x, A1.y, B0.w, B1.x, B1.y,
               Rr[4], Rr[5], Rr[6], Rr[7], pAa, pAb, pBa, pBb);

        fma_q(ha_q + (q+2)*32, hcp_q + (q+2)*16, Rr[8], Rr[9], Rr[10], Rr[11], accA, accB);
        fma_q(ha_q + (q+3)*32, hcp_q + (q+3)*16, Rr[12], Rr[13], Rr[14], Rr[15], accA, accB);

        comp_r(do_p2, q + 6 < 25, A1.z, A1.w, A2.x, B1.z, B1.w, B2.x,
               Rr[8], Rr[9], Rr[10], Rr[11], pAa, pAb, pBa, pBb);
        comp_r(do_p2, q + 7 < 25, A2.y, A2.z, A2.w, B2.y, B2.z, B2.w,
               Rr[12], Rr[13], Rr[14], Rr[15], pAa, pAb, pBa, pBb);
    }

    // ---- c = 11: process chunk 11 (q 44..47), prefetch tail (q 48..49) ----
    {
        uint64_t T0A, T1A, T0B, T1B, U0A, U1A, U0B, U1B;
        {
            const float2* a2 = (const float2*)((const float*)tvA + 144);
            const float2* b2 = (const float2*)((const float*)tvB + 144);
            float2 ua = a2[0], va = a2[1], wa2 = a2[2];
            float2 ub = b2[0], vb = b2[1], wb2 = b2[2];

            fma_q(ha_q + 44*32, hcp_q + 44*16, Rr[0], Rr[1], Rr[2], Rr[3], accA, accB);
            fma_q(ha_q + 45*32, hcp_q + 45*16, Rr[4], Rr[5], Rr[6], Rr[7], accA, accB);

            comp_r(do_p2, false, ua.x, ua.y, va.x, ub.x, ub.y, vb.x,
                   T0A, T1A, T0B, T1B, pAa, pAb, pBa, pBb);
            comp_r(do_p2, false, va.y, wa2.x, wa2.y, vb.y, wb2.x, wb2.y,
                   U0A, U1A, U0B, U1B, pAa, pAb, pBa, pBb);

            fma_q(ha_q + 46*32, hcp_q + 46*16, Rr[8], Rr[9], Rr[10], Rr[11], accA, accB);
            fma_q(ha_q + 47*32, hcp_q + 47*16, Rr[12], Rr[13], Rr[14], Rr[15], accA, accB);
        }
        fma_q(ha_q + 48*32, hcp_q + 48*16, T0A, T1A, T0B, T1B, accA, accB);
        fma_q(ha_q + 49*32, hcp_q + 49*16, U0A, U1A, U0B, U1B, accA, accB);
    }

    // hr-weighted sums over this quarter's 16 heads
    float partA = 0.0f, partB = 0.0f;
    const float* hrq = sh_hr + quarter * 16;
    #pragma unroll
    for (int j = 0; j < 8; j++) {
        float lo, hi;
        asm("mov.b64 {%0, %1}, %2;" : "=f"(lo), "=f"(hi) : "l"(accA[j]));
        partA = fmaf(hrq[2 * j], lo, partA);
        partA = fmaf(hrq[2 * j + 1], hi, partA);
        asm("mov.b64 {%0, %1}, %2;" : "=f"(lo), "=f"(hi) : "l"(accB[j]));
        partB = fmaf(hrq[2 * j], lo, partB);
        partB = fmaf(hrq[2 * j + 1], hi, partB);
    }

    if (quarter != 0) {
        sh_part[(quarter - 1) * WORDS + wA] = partA;
        sh_part[(quarter - 1) * WORDS + wB] = partB;
    }
    __syncthreads();

    double v = 0.0;
    if (quarter == 0) {
        int nA = base + wA;
        if (nA < N) {
            float covf = partA + sh_part[wA] + sh_part[WORDS + wA] + sh_part[2 * WORDS + wA];
            double cov = (double)covf * (double)pAa * (double)pAb;
            float c = coeff[nA];
            v = (double)(c * c) / cov;
        }
        int nB = base + wB;
        if (nB < N) {
            float covf = partB + sh_part[wB] + sh_part[WORDS + wB] + sh_part[2 * WORDS + wB];
            double cov = (double)covf * (double)pBa * (double)pBb;
            float c = coeff[nB];
            v += (double)(c * c) / cov;
        }
        #pragma unroll
        for (int off = 16; off; off >>= 1)
            v += __shfl_down_sync(0xFFFFFFFFu, v, off);
        if (lane == 0) sh_red[group] = v;
    }
    __syncthreads();
    if (tid == 0) {
        double s = 0.0;
        #pragma unroll
        for (int w = 0; w < 4; w++) s += sh_red[w];
        atomicAdd(&g_accum, s);
        __threadfence();
        unsigned int ticket = atomicAdd(&g_count, 1u);
        if (ticket == (unsigned int)(nblocks - 1)) {
            out[0] = (float)g_accum;
        }
    }
}

// ---------------------------------------------------------------------------
extern "C" void kernel_launch(void* const* d_in, const int* in_sizes, int n_in,
                              void* d_out, int out_size) {
    const float* pauli = (const float*)d_in[0];   // [N, 50, 3] f32
    const float* coeff = (const float*)d_in[1];   // [N] f32
    const float* heads = (const float*)d_in[2];   // [64, 50, 3] f32
    const float* hr    = (const float*)d_in[3];   // [64] f32
    const int N = in_sizes[1];

    const size_t smem = (size_t)SMEM_FLOATS * sizeof(float);   // 201536 B
    cudaFuncSetAttribute(main_kernel, cudaFuncAttributeMaxDynamicSharedMemorySize, (int)smem);

    prep_kernel<<<50, 128>>>(heads, hr);
    const int grid = (N + WORDS - 1) / WORDS;
    main_kernel<<<grid, THREADS, smem>>>(pauli, coeff, (float*)d_out, N, grid);
}

// round 16
// speedup vs baseline: 1.1756x; 1.0899x over previous
#include <cuda_runtime.h>
#include <cstdint>

// Problem constants (shapes fixed by the dataset)
#define SQ 50          // qubits
#define SP 3           // pauli basis
#define SS 64          // heads
#define WORDS 256      // words per block
#define THREADS 512    // 16 warps; warp quads split 64 heads, 2 words/thread
#define TROW 156       // padded row stride (28i mod 32: 8-lane LDS.128 phases disjoint)

// Packed heads: ha[q][j(32)][4] = {h0s0,h0s1,h1s0,h1s1}
//               hcp[q][jp(16)][4] = {h2(2jp)s0,h2(2jp)s1, h2(2jp+1)s0,h2(2jp+1)s1}
#define HA_TOTAL (SQ * 128)   // 6400
#define HCP_TOTAL (SQ * 64)   // 3200

// smem float offsets
#define OFF_HCP  HA_TOTAL               // 6400
#define OFF_HR   (OFF_HCP + HCP_TOTAL)  // 9600
#define OFF_PART (OFF_HR + SS)          // 9664 (3*256 = 768)
#define OFF_RED  (OFF_PART + 3*WORDS)   // 10432 (16 floats = 8 doubles)
#define OFF_T    (OFF_RED + 16)         // 10448 (41792 B, 16B aligned)
#define SMEM_FLOATS (OFF_T + WORDS * TROW)   // 50384 floats = 201536 B

__device__ double       g_accum;
__device__ unsigned int g_count;
__device__ float        g_ha[HA_TOTAL];
__device__ float        g_hcp[HCP_TOTAL];
__device__ float        g_hr[SS];

__device__ __forceinline__ float softplus20(float x) {
    float y = x * 20.0f;
    return fmaxf(y, 0.0f) + log1pf(expf(-fabsf(y)));
}

// ---------------------------------------------------------------------------
__global__ void prep_kernel(const float* __restrict__ heads_param,
                            const float* __restrict__ hr_param) {
    const int tid = threadIdx.x;

    if (blockIdx.x == 0 && tid == 0) { g_accum = 0.0; g_count = 0u; }

    __shared__ float s_hr[SS];
    if (tid < SS) s_hr[tid] = softplus20(hr_param[tid]);
    __syncthreads();
    if (blockIdx.x == 0 && tid < SS) {
        float s = 0.0f;
        #pragma unroll
        for (int i = 0; i < SS; i++) s += s_hr[i];
        s = fmaxf(s, 1e-12f);
        g_hr[tid] = (s_hr[tid] / s + 0.001f / (float)SS) / 1.001f;
    }

    const int stride = blockDim.x * gridDim.x;
    for (int i = blockIdx.x * blockDim.x + tid; i < SS * SQ; i += stride) {
        int s = i / SQ;
        int q = i - s * SQ;
        const float* hp = heads_param + (s * SQ + q) * SP;
        float h0 = softplus20(hp[0]);
        float h1 = softplus20(hp[1]);
        float h2 = softplus20(hp[2]);
        float inv = 1.0f / fmaxf(h0 + h1 + h2, 1e-12f);
        h0 *= inv; h1 *= inv; h2 *= inv;
        int j = s >> 1, o = s & 1;
        int jp = j >> 1, jo = j & 1;
        g_ha[q * 128 + j * 4 + 0 + o]       = h0;
        g_ha[q * 128 + j * 4 + 2 + o]       = h1;
        g_hcp[q * 64 + jp * 4 + jo * 2 + o] = h2;
    }
}

// ---------------------------------------------------------------------------
// Per-q step: 2 words x 8 head-pairs. dot = t2c*(h2 + h0*(t0/t2c) + h1*(t1/t2c))
// ---------------------------------------------------------------------------
__device__ __forceinline__ void proc_q2(
    bool do_p2, bool first_half,
    float t0a, float t1a, float t2a,     // word A
    float t0b, float t1b, float t2b,     // word B
    const ulonglong2* __restrict__ ha,   // this q, quarter offset: 8 entries
    const ulonglong2* __restrict__ hcp,  // this q, quarter offset: 4 entries
    uint64_t* __restrict__ accA, uint64_t* __restrict__ accB,
    float& pAa, float& pAb, float& pBa, float& pBb)
{
    float t2ca = fmaxf(t2a, 1e-12f);
    float t2cb = fmaxf(t2b, 1e-12f);
    float ra, rb;
    asm("rcp.approx.f32 %0, %1;" : "=f"(ra) : "f"(t2ca));
    asm("rcp.approx.f32 %0, %1;" : "=f"(rb) : "f"(t2cb));
    float r0a = t0a * ra, r1a = t1a * ra;
    float r0b = t0b * rb, r1b = t1b * rb;
    if (do_p2) {
        if (first_half) { pAa *= t2ca; pBa *= t2cb; }
        else            { pAb *= t2ca; pBb *= t2cb; }
    }

    uint64_t R0A, R1A, R0B, R1B;
    asm("mov.b64 %0, {%1, %1};" : "=l"(R0A) : "f"(r0a));
    asm("mov.b64 %0, {%1, %1};" : "=l"(R1A) : "f"(r1a));
    asm("mov.b64 %0, {%1, %1};" : "=l"(R0B) : "f"(r0b));
    asm("mov.b64 %0, {%1, %1};" : "=l"(R1B) : "f"(r1b));

    #pragma unroll
    for (int jp = 0; jp < 4; jp++) {
        ulonglong2 HcP = hcp[jp];          // {h2(2jp) pair, h2(2jp+1) pair}
        ulonglong2 Ha0 = ha[2 * jp];
        ulonglong2 Ha1 = ha[2 * jp + 1];
        uint64_t dA, dB;
        // j = 2jp
        asm("fma.rn.f32x2 %0, %1, %2, %3;" : "=l"(dA) : "l"(Ha0.x), "l"(R0A), "l"(HcP.x));
        asm("fma.rn.f32x2 %0, %1, %2, %3;" : "=l"(dB) : "l"(Ha0.x), "l"(R0B), "l"(HcP.x));
        asm("fma.rn.f32x2 %0, %1, %2, %3;" : "=l"(dA) : "l"(Ha0.y), "l"(R1A), "l"(dA));
        asm("fma.rn.f32x2 %0, %1, %2, %3;" : "=l"(dB) : "l"(Ha0.y), "l"(R1B), "l"(dB));
        asm("mul.rn.f32x2 %0, %1, %2;" : "=l"(accA[2*jp]) : "l"(accA[2*jp]), "l"(dA));
        asm("mul.rn.f32x2 %0, %1, %2;" : "=l"(accB[2*jp]) : "l"(accB[2*jp]), "l"(dB));
        // j = 2jp+1
        asm("fma.rn.f32x2 %0, %1, %2, %3;" : "=l"(dA) : "l"(Ha1.x), "l"(R0A), "l"(HcP.y));
        asm("fma.rn.f32x2 %0, %1, %2, %3;" : "=l"(dB) : "l"(Ha1.x), "l"(R0B), "l"(HcP.y));
        asm("fma.rn.f32x2 %0, %1, %2, %3;" : "=l"(dA) : "l"(Ha1.y), "l"(R1A), "l"(dA));
        asm("fma.rn.f32x2 %0, %1, %2, %3;" : "=l"(dB) : "l"(Ha1.y), "l"(R1B), "l"(dB));
        asm("mul.rn.f32x2 %0, %1, %2;" : "=l"(accA[2*jp+1]) : "l"(accA[2*jp+1]), "l"(dA));
        asm("mul.rn.f32x2 %0, %1, %2;" : "=l"(accB[2*jp+1]) : "l"(accB[2*jp+1]), "l"(dB));
    }
}

// ---------------------------------------------------------------------------
// Main: warp quad g=wid>>2 covers words [g*64, g*64+64); quarter = wid&3
// handles head pairs quarter*8..+7. Thread words: lane, lane+32.
// Convoy-breaking: group g walks the 12 q-chunks starting at chunk 3g.
// ---------------------------------------------------------------------------
__global__ void __launch_bounds__(THREADS, 1)
main_kernel(const float* __restrict__ pauli,
            const float* __restrict__ coeff,
            float* __restrict__ out,
            int N, int nblocks) {
    extern __shared__ float smem[];
    float*  sh_ha   = smem;
    float*  sh_hcp  = smem + OFF_HCP;
    float*  sh_hr   = smem + OFF_HR;
    float*  sh_part = smem + OFF_PART;
    double* sh_red  = (double*)(smem + OFF_RED);
    float*  sh_t    = smem + OFF_T;

    const int tid  = threadIdx.x;
    const int wid  = tid >> 5;
    const int lane = tid & 31;

    // Stage heads tables
    {
        const float4* src = (const float4*)g_ha;
        float4*       dst = (float4*)sh_ha;
        #pragma unroll
        for (int i = tid; i < HA_TOTAL / 4; i += THREADS) dst[i] = src[i];
        const float4* src2 = (const float4*)g_hcp;
        float4*       dst2 = (float4*)sh_hcp;
        #pragma unroll
        for (int i = tid; i < HCP_TOTAL / 4; i += THREADS) dst2[i] = src2[i];
    }
    if (tid < SS) sh_hr[tid] = g_hr[tid];

    // Stage pauli tile: float2 coalesced reads, padded-row float2 scatter
    const int base  = blockIdx.x * WORDS;
    const int valid = min(WORDS, N - base);
    const float2* gsrc2 = (const float2*)(pauli + (size_t)base * (SQ * SP));
    for (int i = tid; i < valid * 75; i += THREADS) {
        int w = i / 75;
        int k = i - w * 75;
        *(float2*)(sh_t + w * TROW + 2 * k) = gsrc2[i];
    }
    __syncthreads();

    const int quarter = wid & 3;
    const int group   = wid >> 2;
    const int wA = group * 64 + lane;
    const int wB = wA + 32;
    const float* trowA = sh_t + wA * TROW;
    const float* trowB = sh_t + wB * TROW;
    const bool do_p2 = (quarter == 0);   // warp-uniform

    uint64_t accA[8], accB[8];
    #pragma unroll
    for (int j = 0; j < 8; j++) { accA[j] = 0x3F8000003F800000ull; accB[j] = accA[j]; }
    float pAa = 1.0f, pAb = 1.0f, pBa = 1.0f, pBb = 1.0f;

    const ulonglong2* ha_q  = (const ulonglong2*)sh_ha  + quarter * 8;   // + q*32
    const ulonglong2* hcp_q = (const ulonglong2*)sh_hcp + quarter * 4;   // + q*16

    const float4* tvA = (const float4*)trowA;
    const float4* tvB = (const float4*)trowB;

    // Rotated chunk order: group g starts at chunk 3g (offsets 0,3,6,9).
    // Co-resident warps on an SMSP (same quarter, different groups) are
    // permanently out of phase -> no correlated LDS-wait convoy.
    int c = 3 * group;
    #pragma unroll 1
    for (int cc = 0; cc < 12; cc++) {
        float4 A0 = tvA[3*c+0], A1 = tvA[3*c+1], A2 = tvA[3*c+2];
        float4 B0 = tvB[3*c+0], B1 = tvB[3*c+1], B2 = tvB[3*c+2];
        const int q = 4 * c;
        proc_q2(do_p2, q + 0 < 25, A0.x, A0.y, A0.z, B0.x, B0.y, B0.z,
                ha_q + (q+0)*32, hcp_q + (q+0)*16, accA, accB, pAa, pAb, pBa, pBb);
        proc_q2(do_p2, q + 1 < 25, A0.w, A1.x, A1.y, B0.w, B1.x, B1.y,
                ha_q + (q+1)*32, hcp_q + (q+1)*16, accA, accB, pAa, pAb, pBa, pBb);
        proc_q2(do_p2, q + 2 < 25, A1.z, A1.w, A2.x, B1.z, B1.w, B2.x,
                ha_q + (q+2)*32, hcp_q + (q+2)*16, accA, accB, pAa, pAb, pBa, pBb);
        proc_q2(do_p2, q + 3 < 25, A2.y, A2.z, A2.w, B2.y, B2.z, B2.w,
                ha_q + (q+3)*32, hcp_q + (q+3)*16, accA, accB, pAa, pAb, pBa, pBb);
        c++;
        if (c == 12) c = 0;
    }
    {   // q = 48, 49 (floats 144..149, 8B-aligned)
        const float2* a2 = (const float2*)(trowA + 144);
        const float2* b2 = (const float2*)(trowB + 144);
        float2 ua = a2[0], va = a2[1], wa2 = a2[2];
        float2 ub = b2[0], vb = b2[1], wb2 = b2[2];
        proc_q2(do_p2, false, ua.x, ua.y, va.x, ub.x, ub.y, vb.x,
                ha_q + 48*32, hcp_q + 48*16, accA, accB, pAa, pAb, pBa, pBb);
        proc_q2(do_p2, false, va.y, wa2.x, wa2.y, vb.y, wb2.x, wb2.y,
                ha_q + 49*32, hcp_q + 49*16, accA, accB, pAa, pAb, pBa, pBb);
    }

    // hr-weighted sums over this quarter's 16 heads
    float partA = 0.0f, partB = 0.0f;
    const float* hrq = sh_hr + quarter * 16;
    #pragma unroll
    for (int j = 0; j < 8; j++) {
        float lo, hi;
        asm("mov.b64 {%0, %1}, %2;" : "=f"(lo), "=f"(hi) : "l"(accA[j]));
        partA = fmaf(hrq[2 * j], lo, partA);
        partA = fmaf(hrq[2 * j + 1], hi, partA);
        asm("mov.b64 {%0, %1}, %2;" : "=f"(lo), "=f"(hi) : "l"(accB[j]));
        partB = fmaf(hrq[2 * j], lo, partB);
        partB = fmaf(hrq[2 * j + 1], hi, partB);
    }

    if (quarter != 0) {
        sh_part[(quarter - 1) * WORDS + wA] = partA;
        sh_part[(quarter - 1) * WORDS + wB] = partB;
    }
    __syncthreads();

    double v = 0.0;
    if (quarter == 0) {
        int nA = base + wA;
        if (nA < N) {
            float covf = partA + sh_part[wA] + sh_part[WORDS + wA] + sh_part[2 * WORDS + wA];
            double cov = (double)covf * (double)pAa * (double)pAb;
            float c2 = coeff[nA];
            v = (double)(c2 * c2) / cov;
        }
        int nB = base + wB;
        if (nB < N) {
            float covf = partB + sh_part[wB] + sh_part[WORDS + wB] + sh_part[2 * WORDS + wB];
            double cov = (double)covf * (double)pBa * (double)pBb;
            float c2 = coeff[nB];
            v += (double)(c2 * c2) / cov;
        }
        #pragma unroll
        for (int off = 16; off; off >>= 1)
            v += __shfl_down_sync(0xFFFFFFFFu, v, off);
        if (lane == 0) sh_red[group] = v;
    }
    __syncthreads();
    if (tid == 0) {
        double s = 0.0;
        #pragma unroll
        for (int w = 0; w < 4; w++) s += sh_red[w];
        atomicAdd(&g_accum, s);
        __threadfence();
        unsigned int ticket = atomicAdd(&g_count, 1u);
        if (ticket == (unsigned int)(nblocks - 1)) {
            out[0] = (float)g_accum;
        }
    }
}

// ---------------------------------------------------------------------------
extern "C" void kernel_launch(void* const* d_in, const int* in_sizes, int n_in,
                              void* d_out, int out_size) {
    const float* pauli = (const float*)d_in[0];   // [N, 50, 3] f32
    const float* coeff = (const float*)d_in[1];   // [N] f32
    const float* heads = (const float*)d_in[2];   // [64, 50, 3] f32
    const float* hr    = (const float*)d_in[3];   // [64] f32
    const int N = in_sizes[1];

    const size_t smem = (size_t)SMEM_FLOATS * sizeof(float);   // 201536 B
    cudaFuncSetAttribute(main_kernel, cudaFuncAttributeMaxDynamicSharedMemorySize, (int)smem);

    prep_kernel<<<50, 128>>>(heads, hr);
    const int grid = (N + WORDS - 1) / WORDS;
    main_kernel<<<grid, THREADS, smem>>>(pauli, coeff, (float*)d_out, N, grid);
}

// round 17
// speedup vs baseline: 1.1805x; 1.0042x over previous
#include <cuda_runtime.h>
#include <cstdint>

// Problem constants (shapes fixed by the dataset)
#define SQ 50          // qubits
#define SP 3           // pauli basis
#define SS 64          // heads
#define WORDS 256      // words per block
#define THREADS 512    // 16 warps; warp quads split 64 heads, 2 words/thread
#define TROW 156       // padded row stride (28i mod 32: 8-lane LDS.128 phases disjoint)

// Packed heads: ha[q][j(32)][4] = {h0s0,h0s1,h1s0,h1s1}
//               hcp[q][jp(16)][4] = {h2(2jp)s0,h2(2jp)s1, h2(2jp+1)s0,h2(2jp+1)s1}
#define HA_TOTAL (SQ * 128)   // 6400
#define HCP_TOTAL (SQ * 64)   // 3200

// smem float offsets
#define OFF_HCP  HA_TOTAL               // 6400
#define OFF_HR   (OFF_HCP + HCP_TOTAL)  // 9600
#define OFF_PART (OFF_HR + SS)          // 9664 (3*256 = 768)
#define OFF_RED  (OFF_PART + 3*WORDS)   // 10432 (16 floats = 8 doubles)
#define OFF_T    (OFF_RED + 16)         // 10448 (41792 B, 16B aligned)
#define SMEM_FLOATS (OFF_T + WORDS * TROW)   // 50384 floats = 201536 B

__device__ double       g_accum;
__device__ unsigned int g_count;
__device__ float        g_ha[HA_TOTAL];
__device__ float        g_hcp[HCP_TOTAL];
__device__ float        g_hr[SS];

__device__ __forceinline__ float softplus20(float x) {
    float y = x * 20.0f;
    return fmaxf(y, 0.0f) + log1pf(expf(-fabsf(y)));
}

// ---------------------------------------------------------------------------
__global__ void prep_kernel(const float* __restrict__ heads_param,
                            const float* __restrict__ hr_param) {
    const int tid = threadIdx.x;

    if (blockIdx.x == 0 && tid == 0) { g_accum = 0.0; g_count = 0u; }

    __shared__ float s_hr[SS];
    if (tid < SS) s_hr[tid] = softplus20(hr_param[tid]);
    __syncthreads();
    if (blockIdx.x == 0 && tid < SS) {
        float s = 0.0f;
        #pragma unroll
        for (int i = 0; i < SS; i++) s += s_hr[i];
        s = fmaxf(s, 1e-12f);
        g_hr[tid] = (s_hr[tid] / s + 0.001f / (float)SS) / 1.001f;
    }

    const int stride = blockDim.x * gridDim.x;
    for (int i = blockIdx.x * blockDim.x + tid; i < SS * SQ; i += stride) {
        int s = i / SQ;
        int q = i - s * SQ;
        const float* hp = heads_param + (s * SQ + q) * SP;
        float h0 = softplus20(hp[0]);
        float h1 = softplus20(hp[1]);
        float h2 = softplus20(hp[2]);
        float inv = 1.0f / fmaxf(h0 + h1 + h2, 1e-12f);
        h0 *= inv; h1 *= inv; h2 *= inv;
        int j = s >> 1, o = s & 1;
        int jp = j >> 1, jo = j & 1;
        g_ha[q * 128 + j * 4 + 0 + o]       = h0;
        g_ha[q * 128 + j * 4 + 2 + o]       = h1;
        g_hcp[q * 64 + jp * 4 + jo * 2 + o] = h2;
    }
}

// ---------------------------------------------------------------------------
// Per-q step: 2 words x 8 head-pairs. dot = t2c*(h2 + h0*(t0/t2c) + h1*(t1/t2c))
// ---------------------------------------------------------------------------
__device__ __forceinline__ void proc_q2(
    bool do_p2, bool first_half,
    float t0a, float t1a, float t2a,     // word A
    float t0b, float t1b, float t2b,     // word B
    const ulonglong2* __restrict__ ha,   // this q, quarter offset: 8 entries
    const ulonglong2* __restrict__ hcp,  // this q, quarter offset: 4 entries
    uint64_t* __restrict__ accA, uint64_t* __restrict__ accB,
    float& pAa, float& pAb, float& pBa, float& pBb)
{
    float t2ca = fmaxf(t2a, 1e-12f);
    float t2cb = fmaxf(t2b, 1e-12f);
    float ra, rb;
    asm("rcp.approx.f32 %0, %1;" : "=f"(ra) : "f"(t2ca));
    asm("rcp.approx.f32 %0, %1;" : "=f"(rb) : "f"(t2cb));
    float r0a = t0a * ra, r1a = t1a * ra;
    float r0b = t0b * rb, r1b = t1b * rb;
    if (do_p2) {
        if (first_half) { pAa *= t2ca; pBa *= t2cb; }
        else            { pAb *= t2ca; pBb *= t2cb; }
    }

    uint64_t R0A, R1A, R0B, R1B;
    asm("mov.b64 %0, {%1, %1};" : "=l"(R0A) : "f"(r0a));
    asm("mov.b64 %0, {%1, %1};" : "=l"(R1A) : "f"(r1a));
    asm("mov.b64 %0, {%1, %1};" : "=l"(R0B) : "f"(r0b));
    asm("mov.b64 %0, {%1, %1};" : "=l"(R1B) : "f"(r1b));

    #pragma unroll
    for (int jp = 0; jp < 4; jp++) {
        ulonglong2 HcP = hcp[jp];          // {h2(2jp) pair, h2(2jp+1) pair}
        ulonglong2 Ha0 = ha[2 * jp];
        ulonglong2 Ha1 = ha[2 * jp + 1];
        uint64_t dA, dB;
        // j = 2jp
        asm("fma.rn.f32x2 %0, %1, %2, %3;" : "=l"(dA) : "l"(Ha0.x), "l"(R0A), "l"(HcP.x));
        asm("fma.rn.f32x2 %0, %1, %2, %3;" : "=l"(dB) : "l"(Ha0.x), "l"(R0B), "l"(HcP.x));
        asm("fma.rn.f32x2 %0, %1, %2, %3;" : "=l"(dA) : "l"(Ha0.y), "l"(R1A), "l"(dA));
        asm("fma.rn.f32x2 %0, %1, %2, %3;" : "=l"(dB) : "l"(Ha0.y), "l"(R1B), "l"(dB));
        asm("mul.rn.f32x2 %0, %1, %2;" : "=l"(accA[2*jp]) : "l"(accA[2*jp]), "l"(dA));
        asm("mul.rn.f32x2 %0, %1, %2;" : "=l"(accB[2*jp]) : "l"(accB[2*jp]), "l"(dB));
        // j = 2jp+1
        asm("fma.rn.f32x2 %0, %1, %2, %3;" : "=l"(dA) : "l"(Ha1.x), "l"(R0A), "l"(HcP.y));
        asm("fma.rn.f32x2 %0, %1, %2, %3;" : "=l"(dB) : "l"(Ha1.x), "l"(R0B), "l"(HcP.y));
        asm("fma.rn.f32x2 %0, %1, %2, %3;" : "=l"(dA) : "l"(Ha1.y), "l"(R1A), "l"(dA));
        asm("fma.rn.f32x2 %0, %1, %2, %3;" : "=l"(dB) : "l"(Ha1.y), "l"(R1B), "l"(dB));
        asm("mul.rn.f32x2 %0, %1, %2;" : "=l"(accA[2*jp+1]) : "l"(accA[2*jp+1]), "l"(dA));
        asm("mul.rn.f32x2 %0, %1, %2;" : "=l"(accB[2*jp+1]) : "l"(accB[2*jp+1]), "l"(dB));
    }
}

// ---------------------------------------------------------------------------
// Main: warp quad g=wid>>2 covers words [g*64, g*64+64); quarter = wid&3
// handles head pairs quarter*8..+7. Thread words: lane, lane+32.
// Convoy-breaking: group g walks the 12 q-chunks starting at chunk 3g.
// ---------------------------------------------------------------------------
__global__ void __launch_bounds__(THREADS, 1)
main_kernel(const float* __restrict__ pauli,
            const float* __restrict__ coeff,
            float* __restrict__ out,
            int N, int nblocks) {
    extern __shared__ float smem[];
    float*  sh_ha   = smem;
    float*  sh_hcp  = smem + OFF_HCP;
    float*  sh_hr   = smem + OFF_HR;
    float*  sh_part = smem + OFF_PART;
    double* sh_red  = (double*)(smem + OFF_RED);
    float*  sh_t    = smem + OFF_T;

    const int tid  = threadIdx.x;
    const int wid  = tid >> 5;
    const int lane = tid & 31;

    // Stage heads tables
    {
        const float4* src = (const float4*)g_ha;
        float4*       dst = (float4*)sh_ha;
        #pragma unroll
        for (int i = tid; i < HA_TOTAL / 4; i += THREADS) dst[i] = src[i];
        const float4* src2 = (const float4*)g_hcp;
        float4*       dst2 = (float4*)sh_hcp;
        #pragma unroll
        for (int i = tid; i < HCP_TOTAL / 4; i += THREADS) dst2[i] = src2[i];
    }
    if (tid < SS) sh_hr[tid] = g_hr[tid];

    // Stage pauli tile: float2 coalesced reads, padded-row float2 scatter
    const int base  = blockIdx.x * WORDS;
    const int valid = min(WORDS, N - base);
    const float2* gsrc2 = (const float2*)(pauli + (size_t)base * (SQ * SP));
    for (int i = tid; i < valid * 75; i += THREADS) {
        int w = i / 75;
        int k = i - w * 75;
        *(float2*)(sh_t + w * TROW + 2 * k) = gsrc2[i];
    }
    __syncthreads();

    const int quarter = wid & 3;
    const int group   = wid >> 2;
    const int wA = group * 64 + lane;
    const int wB = wA + 32;
    const float* trowA = sh_t + wA * TROW;
    const float* trowB = sh_t + wB * TROW;
    const bool do_p2 = (quarter == 0);   // warp-uniform

    uint64_t accA[8], accB[8];
    #pragma unroll
    for (int j = 0; j < 8; j++) { accA[j] = 0x3F8000003F800000ull; accB[j] = accA[j]; }
    float pAa = 1.0f, pAb = 1.0f, pBa = 1.0f, pBb = 1.0f;

    const ulonglong2* ha_q  = (const ulonglong2*)sh_ha  + quarter * 8;   // + q*32
    const ulonglong2* hcp_q = (const ulonglong2*)sh_hcp + quarter * 4;   // + q*16

    const float4* tvA = (const float4*)trowA;
    const float4* tvB = (const float4*)trowB;

    // Rotated chunk order: group g starts at chunk 3g (offsets 0,3,6,9).
    // Co-resident warps on an SMSP (same quarter, different groups) are
    // permanently out of phase -> no correlated LDS-wait convoy.
    int c = 3 * group;
    #pragma unroll 1
    for (int cc = 0; cc < 12; cc++) {
        float4 A0 = tvA[3*c+0], A1 = tvA[3*c+1], A2 = tvA[3*c+2];
        float4 B0 = tvB[3*c+0], B1 = tvB[3*c+1], B2 = tvB[3*c+2];
        const int q = 4 * c;
        proc_q2(do_p2, q + 0 < 25, A0.x, A0.y, A0.z, B0.x, B0.y, B0.z,
                ha_q + (q+0)*32, hcp_q + (q+0)*16, accA, accB, pAa, pAb, pBa, pBb);
        proc_q2(do_p2, q + 1 < 25, A0.w, A1.x, A1.y, B0.w, B1.x, B1.y,
                ha_q + (q+1)*32, hcp_q + (q+1)*16, accA, accB, pAa, pAb, pBa, pBb);
        proc_q2(do_p2, q + 2 < 25, A1.z, A1.w, A2.x, B1.z, B1.w, B2.x,
                ha_q + (q+2)*32, hcp_q + (q+2)*16, accA, accB, pAa, pAb, pBa, pBb);
        proc_q2(do_p2, q + 3 < 25, A2.y, A2.z, A2.w, B2.y, B2.z, B2.w,
                ha_q + (q+3)*32, hcp_q + (q+3)*16, accA, accB, pAa, pAb, pBa, pBb);
        c++;
        if (c == 12) c = 0;
    }
    {   // q = 48, 49 (floats 144..149, 8B-aligned)
        const float2* a2 = (const float2*)(trowA + 144);
        const float2* b2 = (const float2*)(trowB + 144);
        float2 ua = a2[0], va = a2[1], wa2 = a2[2];
        float2 ub = b2[0], vb = b2[1], wb2 = b2[2];
        proc_q2(do_p2, false, ua.x, ua.y, va.x, ub.x, ub.y, vb.x,
                ha_q + 48*32, hcp_q + 48*16, accA, accB, pAa, pAb, pBa, pBb);
        proc_q2(do_p2, false, va.y, wa2.x, wa2.y, vb.y, wb2.x, wb2.y,
                ha_q + 49*32, hcp_q + 49*16, accA, accB, pAa, pAb, pBa, pBb);
    }

    // hr-weighted sums over this quarter's 16 heads
    float partA = 0.0f, partB = 0.0f;
    const float* hrq = sh_hr + quarter * 16;
    #pragma unroll
    for (int j = 0; j < 8; j++) {
        float lo, hi;
        asm("mov.b64 {%0, %1}, %2;" : "=f"(lo), "=f"(hi) : "l"(accA[j]));
        partA = fmaf(hrq[2 * j], lo, partA);
        partA = fmaf(hrq[2 * j + 1], hi, partA);
        asm("mov.b64 {%0, %1}, %2;" : "=f"(lo), "=f"(hi) : "l"(accB[j]));
        partB = fmaf(hrq[2 * j], lo, partB);
        partB = fmaf(hrq[2 * j + 1], hi, partB);
    }

    if (quarter != 0) {
        sh_part[(quarter - 1) * WORDS + wA] = partA;
        sh_part[(quarter - 1) * WORDS + wB] = partB;
    }
    __syncthreads();

    double v = 0.0;
    if (quarter == 0) {
        int nA = base + wA;
        if (nA < N) {
            float covf = partA + sh_part[wA] + sh_part[WORDS + wA] + sh_part[2 * WORDS + wA];
            double cov = (double)covf * (double)pAa * (double)pAb;
            float c2 = coeff[nA];
            v = (double)(c2 * c2) / cov;
        }
        int nB = base + wB;
        if (nB < N) {
            float covf = partB + sh_part[wB] + sh_part[WORDS + wB] + sh_part[2 * WORDS + wB];
            double cov = (double)covf * (double)pBa * (double)pBb;
            float c2 = coeff[nB];
            v += (double)(c2 * c2) / cov;
        }
        #pragma unroll
        for (int off = 16; off; off >>= 1)
            v += __shfl_down_sync(0xFFFFFFFFu, v, off);
        if (lane == 0) sh_red[group] = v;
    }
    __syncthreads();
    if (tid == 0) {
        double s = 0.0;
        #pragma unroll
        for (int w = 0; w < 4; w++) s += sh_red[w];
        atomicAdd(&g_accum, s);
        __threadfence();
        unsigned int ticket = atomicAdd(&g_count, 1u);
        if (ticket == (unsigned int)(nblocks - 1)) {
            out[0] = (float)g_accum;
        }
    }
}

// ---------------------------------------------------------------------------
extern "C" void kernel_launch(void* const* d_in, const int* in_sizes, int n_in,
                              void* d_out, int out_size) {
    const float* pauli = (const float*)d_in[0];   // [N, 50, 3] f32
    const float* coeff = (const float*)d_in[1];   // [N] f32
    const float* heads = (const float*)d_in[2];   // [64, 50, 3] f32
    const float* hr    = (const float*)d_in[3];   // [64] f32
    const int N = in_sizes[1];

    const size_t smem = (size_t)SMEM_FLOATS * sizeof(float);   // 201536 B
    cudaFuncSetAttribute(main_kernel, cudaFuncAttributeMaxDynamicSharedMemorySize, (int)smem);

    prep_kernel<<<50, 128>>>(heads, hr);
    const int grid = (N + WORDS - 1) / WORDS;
    main_kernel<<<grid, THREADS, smem>>>(pauli, coeff, (float*)d_out, N, grid);
}